// round 9
// baseline (speedup 1.0000x reference)
#include <cuda_runtime.h>
#include <cuda_fp16.h>
#include <float.h>
#include <stdint.h>

// VectorQuantizer via mma.sync (fp16, fp32 accum) + fused argmin.
// out[n] = (float) argmin_k ( e_sq[k] - 2 * <x_n, e_k> )
// cross via 3-product fp16 split: xh*eh + xh*el + xl*eh (residual ~2^-22).
// R9: 8 warps/CTA (2M x 4N, 32x16 warp tiles), 2 CTAs/SM -> 4 warps/SMSP
// for MMA latency hiding. Regs capped at 128 via __launch_bounds__(256,2).

#define DD      256
#define NMAX    32768
#define KMAX    8192

#define TILE_M  64        // rows per CTA
#define TILE_NC 64        // codes per K-tile
#define BD      64        // depth per chunk
#define NT      256       // 8 warps: 2 (M) x 4 (N)

// dynamic smem layout (bytes)
#define XSTRIDE       264                      // fp16 per x row (256 + 8 pad)
#define ESTRIDE       72                       // fp16 per e row (64 + 8 pad)
#define XSPLIT_BYTES  (TILE_M * XSTRIDE * 2)   // 33792
#define SM_X          0                        // [split][64][264]
#define ESPLIT_BYTES  (TILE_NC * ESTRIDE * 2)  // 9216
#define EBUF_BYTES    (2 * ESPLIT_BYTES)       // 18432 (hi+lo)
#define SM_E          (2 * XSPLIT_BYTES)       // ring of 2 bufs
#define SMEM_BYTES    (SM_E + 2 * EBUF_BYTES)  // 104448

__device__ float  g_esq[KMAX];
__device__ __half g_xh[(size_t)NMAX * DD];
__device__ __half g_xl[(size_t)NMAX * DD];
__device__ __half g_eh[(size_t)KMAX * DD];
__device__ __half g_el[(size_t)KMAX * DD];

// ---------------------------------------------------------------------------
// helpers
// ---------------------------------------------------------------------------
__device__ __forceinline__ uint32_t smem_u32(const void* p) {
    uint32_t a;
    asm("{ .reg .u64 t; cvta.to.shared.u64 t, %1; cvt.u32.u64 %0, t; }"
        : "=r"(a) : "l"(p));
    return a;
}
__device__ __forceinline__ void ldsm_x4(uint32_t* r, uint32_t addr) {
    asm volatile("ldmatrix.sync.aligned.m8n8.x4.shared.b16 {%0,%1,%2,%3}, [%4];"
                 : "=r"(r[0]), "=r"(r[1]), "=r"(r[2]), "=r"(r[3]) : "r"(addr));
}
__device__ __forceinline__ void mma_f16(float* d, const uint32_t* a, uint32_t b0, uint32_t b1) {
    asm volatile(
        "mma.sync.aligned.m16n8k16.row.col.f32.f16.f16.f32 "
        "{%0,%1,%2,%3}, {%4,%5,%6,%7}, {%8,%9}, {%0,%1,%2,%3};"
        : "+f"(d[0]), "+f"(d[1]), "+f"(d[2]), "+f"(d[3])
        : "r"(a[0]), "r"(a[1]), "r"(a[2]), "r"(a[3]), "r"(b0), "r"(b1));
}
__device__ __forceinline__ void cp16(uint32_t dst, const void* src) {
    asm volatile("cp.async.cg.shared.global [%0], [%1], 16;"
                 :: "r"(dst), "l"(__cvta_generic_to_global(src)) : "memory");
}

// ---------------------------------------------------------------------------
// precompute kernels
// ---------------------------------------------------------------------------
__global__ void esq_kernel(const float* __restrict__ e, int K) {
    int k = blockIdx.x * blockDim.x + threadIdx.x;
    if (k >= K) return;
    const float* row = e + (size_t)k * DD;
    float s = 0.0f;
#pragma unroll 8
    for (int d = 0; d < DD; d++) s += row[d] * row[d];
    g_esq[k] = s;
}
__global__ void split_kernel(const float* __restrict__ src,
                             __half* __restrict__ hi,
                             __half* __restrict__ lo, int n) {
    int i = blockIdx.x * blockDim.x + threadIdx.x;
    if (i >= n) return;
    float v = src[i];
    __half h = __float2half(v);
    hi[i] = h;
    lo[i] = __float2half(v - __half2float(h));
}

// ---------------------------------------------------------------------------
// main kernel: 8 warps (2M x 4N), 2 CTAs/SM
// ---------------------------------------------------------------------------
__global__ __launch_bounds__(NT, 2)
void vq_mma_kernel(float* __restrict__ out, int N, int K) {
    extern __shared__ __align__(128) char smem[];
    __shared__ float sd[4][TILE_M];
    __shared__ int   si[4][TILE_M];

    const int tid  = threadIdx.x;
    const int wid  = tid >> 5;
    const int lane = tid & 31;
    const int gr   = lane >> 2;       // 0..7
    const int tc   = lane & 3;        // 0..3
    const int mw   = wid >> 2;        // 0..1  (M slice: mw*32)
    const int nw   = wid & 3;         // 0..3  (N slice: nw*16)
    const int row0 = blockIdx.x * TILE_M;

    const uint32_t smb = smem_u32(smem);
    const uint32_t smX = smb + SM_X;
    const uint32_t smE = smb + SM_E;

    // ---- load resident x tiles (hi/lo), row-major with padded stride ----
    {
        const uint4* xh4 = (const uint4*)g_xh;
        const uint4* xl4 = (const uint4*)g_xl;
#pragma unroll
        for (int t = 0; t < 8; t++) {
            int idx = tid + t * NT;          // 0..2047
            int r   = idx >> 5;              // row 0..63
            int g16 = idx & 31;              // 16B granule (32 per 512B row)
            size_t g = (size_t)(row0 + r) * 32 + g16;
            uint32_t off = (uint32_t)r * (XSTRIDE * 2) + (uint32_t)g16 * 16;
            *(uint4*)(smem + SM_X + off)                = xh4[g];
            *(uint4*)(smem + SM_X + XSPLIT_BYTES + off) = xl4[g];
        }
    }

    // ---- lane-dependent ldmatrix base offsets ----
    const uint32_t a_lane = (uint32_t)(lane & 15) * (XSTRIDE * 2) + (uint32_t)(lane & 16);
    const uint32_t b_lane = ((uint32_t)((lane & 7) + ((lane & 16) >> 1))) * (ESTRIDE * 2)
                          + (uint32_t)((lane & 8) << 1);

    const int n_tiles = K / TILE_NC;
    const int G       = n_tiles * (DD / BD);      // chunks

    // per-lane running argmin: 4 row-slots (mt*2 + half)
    float best_d[4];
    int   best_i[4];
#pragma unroll
    for (int s = 0; s < 4; s++) { best_d[s] = FLT_MAX; best_i[s] = 0; }

    float acc[2][2][4];   // [mt][n][frag]: 32 rows x 16 cols per warp

    // ---- e-chunk loader (cp.async, 4 x 16B per thread) ----
    auto issue_load = [&](int g) {
        int c   = g & 3;
        int kt0 = (g >> 2) * TILE_NC;
        uint32_t dbase = smE + (uint32_t)(g & 1) * EBUF_BYTES;
#pragma unroll
        for (int t = 0; t < 4; t++) {
            int idx = tid + t * NT;          // 0..1023
            int sp  = idx >> 9;              // split
            int rem = idx & 511;
            int j   = rem >> 3;              // code row 0..63
            int g16 = rem & 7;               // 16B granule
            const __half* src =
                (sp ? g_el : g_eh) + (size_t)(kt0 + j) * DD + c * BD + g16 * 8;
            uint32_t dst = dbase + (uint32_t)sp * ESPLIT_BYTES
                         + (uint32_t)j * (ESTRIDE * 2) + (uint32_t)g16 * 16;
            cp16(dst, src);
        }
        asm volatile("cp.async.commit_group;" ::: "memory");
    };

    issue_load(0);

    for (int g = 0; g < G; g++) {
        const int c   = g & 3;
        const int kt  = g >> 2;
        const int kt0 = kt * TILE_NC;

        if (g + 1 < G) {
            issue_load(g + 1);
            asm volatile("cp.async.wait_group 1;" ::: "memory");
        } else {
            asm volatile("cp.async.wait_group 0;" ::: "memory");
        }
        __syncthreads();   // buffer (g&1) ready; x tile visible (iter 0)

        if (c == 0) {
#pragma unroll
            for (int mt = 0; mt < 2; mt++)
#pragma unroll
                for (int n = 0; n < 2; n++)
#pragma unroll
                    for (int v = 0; v < 4; v++) acc[mt][n][v] = 0.0f;
        }

        const uint32_t eb = smE + (uint32_t)(g & 1) * EBUF_BYTES;

#pragma unroll
        for (int ks = 0; ks < 4; ks++) {
            // A fragments (hi/lo) for 2 m-tiles
            uint32_t ah[2][4], al[2][4];
#pragma unroll
            for (int mt = 0; mt < 2; mt++) {
                uint32_t base = smX + a_lane
                              + (uint32_t)(mw * 32 + mt * 16) * (XSTRIDE * 2)
                              + (uint32_t)(c * BD + ks * 16) * 2;
                ldsm_x4(ah[mt], base);
                ldsm_x4(al[mt], base + XSPLIT_BYTES);
            }
            // B fragments (hi/lo): one NON-trans x4 per split -> 16 codes
            uint32_t bh[4], bl[4];
            {
                uint32_t base = eb + b_lane
                              + (uint32_t)(nw * 16) * (ESTRIDE * 2)
                              + (uint32_t)(ks * 16) * 2;
                ldsm_x4(bh, base);
                ldsm_x4(bl, base + ESPLIT_BYTES);
            }
#pragma unroll
            for (int mt = 0; mt < 2; mt++)
#pragma unroll
                for (int n = 0; n < 2; n++) {
                    uint32_t b0h = bh[n * 2], b1h = bh[n * 2 + 1];
                    uint32_t b0l = bl[n * 2], b1l = bl[n * 2 + 1];
                    mma_f16(acc[mt][n], ah[mt], b0h, b1h);   // hi*hi
                    mma_f16(acc[mt][n], ah[mt], b0l, b1l);   // hi*lo
                    mma_f16(acc[mt][n], al[mt], b0h, b1h);   // lo*hi
                }
        }

        // ---- per-tile argmin epilogue (registers only) ----
        if (c == 3) {
            const int kb = kt0 + nw * 16;
#pragma unroll
            for (int n = 0; n < 2; n++) {
                const int c0 = kb + n * 8 + 2 * tc;
                float2 es = *(const float2*)&g_esq[c0];
#pragma unroll
                for (int mt = 0; mt < 2; mt++) {
                    float d0 = fmaf(-2.0f, acc[mt][n][0], es.x);
                    float d1 = fmaf(-2.0f, acc[mt][n][1], es.y);
                    float d2 = fmaf(-2.0f, acc[mt][n][2], es.x);
                    float d3 = fmaf(-2.0f, acc[mt][n][3], es.y);
                    int s0 = mt * 2, s1 = mt * 2 + 1;
                    if (d0 < best_d[s0]) { best_d[s0] = d0; best_i[s0] = c0; }
                    if (d1 < best_d[s0]) { best_d[s0] = d1; best_i[s0] = c0 + 1; }
                    if (d2 < best_d[s1]) { best_d[s1] = d2; best_i[s1] = c0; }
                    if (d3 < best_d[s1]) { best_d[s1] = d3; best_i[s1] = c0 + 1; }
                }
            }
        }
        __syncthreads();   // reads of buffer (g&1) done before refill
    }

    // ---- reduce across the 4 tc-lanes of each row group ----
#pragma unroll
    for (int s = 0; s < 4; s++) {
        float d = best_d[s];
        int   i = best_i[s];
#pragma unroll
        for (int off = 1; off <= 2; off <<= 1) {
            float od = __shfl_xor_sync(0xffffffffu, d, off);
            int   oi = __shfl_xor_sync(0xffffffffu, i, off);
            if (od < d || (od == d && oi < i)) { d = od; i = oi; }
        }
        if (tc == 0) {
            int row_local = mw * 32 + (s >> 1) * 16 + (s & 1) * 8 + gr;
            sd[nw][row_local] = d;
            si[nw][row_local] = i;
        }
    }
    __syncthreads();

    // ---- combine the four N-warps, write float32 indices ----
    if (tid < TILE_M) {
        float bd = sd[0][tid];
        int   bi = si[0][tid];
#pragma unroll
        for (int w = 1; w < 4; w++) {
            float d2 = sd[w][tid];
            int   i2 = si[w][tid];
            if (d2 < bd || (d2 == bd && i2 < bi)) { bd = d2; bi = i2; }
        }
        out[row0 + tid] = (float)bi;
    }
}

// ---------------------------------------------------------------------------
// launch
// ---------------------------------------------------------------------------
extern "C" void kernel_launch(void* const* d_in, const int* in_sizes, int n_in,
                              void* d_out, int out_size) {
    // `inputs` is the larger buffer (N=32768 rows vs K=8192 rows).
    const float* x;
    const float* e;
    int N, K;
    if (in_sizes[0] >= in_sizes[1]) {
        x = (const float*)d_in[0]; N = in_sizes[0] / DD;
        e = (const float*)d_in[1]; K = in_sizes[1] / DD;
    } else {
        x = (const float*)d_in[1]; N = in_sizes[1] / DD;
        e = (const float*)d_in[0]; K = in_sizes[0] / DD;
    }
    float* out = (float*)d_out;

    __half *xh, *xl, *eh, *el;
    cudaGetSymbolAddress((void**)&xh, g_xh);
    cudaGetSymbolAddress((void**)&xl, g_xl);
    cudaGetSymbolAddress((void**)&eh, g_eh);
    cudaGetSymbolAddress((void**)&el, g_el);

    const int nx = N * DD, ne = K * DD;
    split_kernel<<<(nx + 255) / 256, 256>>>(x, xh, xl, nx);
    split_kernel<<<(ne + 255) / 256, 256>>>(e, eh, el, ne);
    esq_kernel<<<(K + 255) / 256, 256>>>(e, K);

    cudaFuncSetAttribute(vq_mma_kernel,
                         cudaFuncAttributeMaxDynamicSharedMemorySize, SMEM_BYTES);
    vq_mma_kernel<<<N / TILE_M, NT, SMEM_BYTES>>>(out, N, K);
}

// round 10
// speedup vs baseline: 1.0057x; 1.0057x over previous
#include <cuda_runtime.h>
#include <cuda_fp16.h>
#include <float.h>
#include <stdint.h>

// VectorQuantizer via mma.sync (fp16) + fused argmin, mixed-precision accum.
// out[n] = (float) argmin_k ( e_sq[k] - 2 * <x_n, e_k> )
// cross = xh*eh (fp32 accum, half-rate) + [xh*el + xl*eh] (fp16 accum,
// full-rate; corrections are ~2^-11 scale so fp16 accumulation error ~2e-5,
// below the fp32 reference's own noise). 3-product split residual ~2^-22.

#define DD      256
#define NMAX    32768
#define KMAX    8192

#define TILE_M  64        // rows per CTA
#define TILE_NC 64        // codes per K-tile
#define BD      64        // depth per chunk
#define NT      256       // 8 warps: 2 (M) x 4 (N)

// dynamic smem layout (bytes)
#define XSTRIDE       264                      // fp16 per x row (256 + 8 pad)
#define ESTRIDE       72                       // fp16 per e row (64 + 8 pad)
#define XSPLIT_BYTES  (TILE_M * XSTRIDE * 2)   // 33792
#define SM_X          0                        // [split][64][264]
#define ESPLIT_BYTES  (TILE_NC * ESTRIDE * 2)  // 9216
#define EBUF_BYTES    (2 * ESPLIT_BYTES)       // 18432 (hi+lo)
#define SM_E          (2 * XSPLIT_BYTES)       // ring of 2 bufs
#define SMEM_BYTES    (SM_E + 2 * EBUF_BYTES)  // 104448

__device__ float  g_esq[KMAX];
__device__ __half g_xh[(size_t)NMAX * DD];
__device__ __half g_xl[(size_t)NMAX * DD];
__device__ __half g_eh[(size_t)KMAX * DD];
__device__ __half g_el[(size_t)KMAX * DD];

// ---------------------------------------------------------------------------
// helpers
// ---------------------------------------------------------------------------
__device__ __forceinline__ uint32_t smem_u32(const void* p) {
    uint32_t a;
    asm("{ .reg .u64 t; cvta.to.shared.u64 t, %1; cvt.u32.u64 %0, t; }"
        : "=r"(a) : "l"(p));
    return a;
}
__device__ __forceinline__ void ldsm_x4(uint32_t* r, uint32_t addr) {
    asm volatile("ldmatrix.sync.aligned.m8n8.x4.shared.b16 {%0,%1,%2,%3}, [%4];"
                 : "=r"(r[0]), "=r"(r[1]), "=r"(r[2]), "=r"(r[3]) : "r"(addr));
}
// fp32-accumulate (half-rate) — used only for the hi*hi product
__device__ __forceinline__ void mma_f32acc(float* d, const uint32_t* a, uint32_t b0, uint32_t b1) {
    asm volatile(
        "mma.sync.aligned.m16n8k16.row.col.f32.f16.f16.f32 "
        "{%0,%1,%2,%3}, {%4,%5,%6,%7}, {%8,%9}, {%0,%1,%2,%3};"
        : "+f"(d[0]), "+f"(d[1]), "+f"(d[2]), "+f"(d[3])
        : "r"(a[0]), "r"(a[1]), "r"(a[2]), "r"(a[3]), "r"(b0), "r"(b1));
}
// fp16-accumulate (full-rate) — used for the small correction products
__device__ __forceinline__ void mma_f16acc(uint32_t* d, const uint32_t* a, uint32_t b0, uint32_t b1) {
    asm volatile(
        "mma.sync.aligned.m16n8k16.row.col.f16.f16.f16.f16 "
        "{%0,%1}, {%2,%3,%4,%5}, {%6,%7}, {%0,%1};"
        : "+r"(d[0]), "+r"(d[1])
        : "r"(a[0]), "r"(a[1]), "r"(a[2]), "r"(a[3]), "r"(b0), "r"(b1));
}
__device__ __forceinline__ void cp16(uint32_t dst, const void* src) {
    asm volatile("cp.async.cg.shared.global [%0], [%1], 16;"
                 :: "r"(dst), "l"(__cvta_generic_to_global(src)) : "memory");
}

// ---------------------------------------------------------------------------
// precompute kernels
// ---------------------------------------------------------------------------
__global__ void esq_kernel(const float* __restrict__ e, int K) {
    int k = blockIdx.x * blockDim.x + threadIdx.x;
    if (k >= K) return;
    const float* row = e + (size_t)k * DD;
    float s = 0.0f;
#pragma unroll 8
    for (int d = 0; d < DD; d++) s += row[d] * row[d];
    g_esq[k] = s;
}
__global__ void split_kernel(const float* __restrict__ src,
                             __half* __restrict__ hi,
                             __half* __restrict__ lo, int n) {
    int i = blockIdx.x * blockDim.x + threadIdx.x;
    if (i >= n) return;
    float v = src[i];
    __half h = __float2half(v);
    hi[i] = h;
    lo[i] = __float2half(v - __half2float(h));
}

// ---------------------------------------------------------------------------
// main kernel: 8 warps (2M x 4N), 2 CTAs/SM
// ---------------------------------------------------------------------------
__global__ __launch_bounds__(NT, 2)
void vq_mma_kernel(float* __restrict__ out, int N, int K) {
    extern __shared__ __align__(128) char smem[];
    __shared__ float sd[4][TILE_M];
    __shared__ int   si[4][TILE_M];

    const int tid  = threadIdx.x;
    const int wid  = tid >> 5;
    const int lane = tid & 31;
    const int gr   = lane >> 2;       // 0..7
    const int tc   = lane & 3;        // 0..3
    const int mw   = wid >> 2;        // 0..1  (M slice: mw*32)
    const int nw   = wid & 3;         // 0..3  (N slice: nw*16)
    const int row0 = blockIdx.x * TILE_M;

    const uint32_t smb = smem_u32(smem);
    const uint32_t smX = smb + SM_X;
    const uint32_t smE = smb + SM_E;

    // ---- load resident x tiles (hi/lo), row-major with padded stride ----
    {
        const uint4* xh4 = (const uint4*)g_xh;
        const uint4* xl4 = (const uint4*)g_xl;
#pragma unroll
        for (int t = 0; t < 8; t++) {
            int idx = tid + t * NT;          // 0..2047
            int r   = idx >> 5;              // row 0..63
            int g16 = idx & 31;              // 16B granule (32 per 512B row)
            size_t g = (size_t)(row0 + r) * 32 + g16;
            uint32_t off = (uint32_t)r * (XSTRIDE * 2) + (uint32_t)g16 * 16;
            *(uint4*)(smem + SM_X + off)                = xh4[g];
            *(uint4*)(smem + SM_X + XSPLIT_BYTES + off) = xl4[g];
        }
    }

    // ---- lane-dependent ldmatrix base offsets ----
    const uint32_t a_lane = (uint32_t)(lane & 15) * (XSTRIDE * 2) + (uint32_t)(lane & 16);
    const uint32_t b_lane = ((uint32_t)((lane & 7) + ((lane & 16) >> 1))) * (ESTRIDE * 2)
                          + (uint32_t)((lane & 8) << 1);

    const int n_tiles = K / TILE_NC;
    const int G       = n_tiles * (DD / BD);      // chunks

    // per-lane running argmin: 4 row-slots (mt*2 + half)
    float best_d[4];
    int   best_i[4];
#pragma unroll
    for (int s = 0; s < 4; s++) { best_d[s] = FLT_MAX; best_i[s] = 0; }

    float    acc[2][2][4];    // hi*hi, fp32 accum
    uint32_t accl[2][2][2];   // xh*el + xl*eh, fp16 accum (packed half2 x2)

    // ---- e-chunk loader (cp.async, 4 x 16B per thread) ----
    auto issue_load = [&](int g) {
        int c   = g & 3;
        int kt0 = (g >> 2) * TILE_NC;
        uint32_t dbase = smE + (uint32_t)(g & 1) * EBUF_BYTES;
#pragma unroll
        for (int t = 0; t < 4; t++) {
            int idx = tid + t * NT;          // 0..1023
            int sp  = idx >> 9;              // split
            int rem = idx & 511;
            int j   = rem >> 3;              // code row 0..63
            int g16 = rem & 7;               // 16B granule
            const __half* src =
                (sp ? g_el : g_eh) + (size_t)(kt0 + j) * DD + c * BD + g16 * 8;
            uint32_t dst = dbase + (uint32_t)sp * ESPLIT_BYTES
                         + (uint32_t)j * (ESTRIDE * 2) + (uint32_t)g16 * 16;
            cp16(dst, src);
        }
        asm volatile("cp.async.commit_group;" ::: "memory");
    };

    issue_load(0);

    for (int g = 0; g < G; g++) {
        const int c   = g & 3;
        const int kt  = g >> 2;
        const int kt0 = kt * TILE_NC;

        if (g + 1 < G) {
            issue_load(g + 1);
            asm volatile("cp.async.wait_group 1;" ::: "memory");
        } else {
            asm volatile("cp.async.wait_group 0;" ::: "memory");
        }
        __syncthreads();   // buffer (g&1) ready; x tile visible (iter 0)

        if (c == 0) {
#pragma unroll
            for (int mt = 0; mt < 2; mt++)
#pragma unroll
                for (int n = 0; n < 2; n++) {
#pragma unroll
                    for (int v = 0; v < 4; v++) acc[mt][n][v] = 0.0f;
                    accl[mt][n][0] = 0u; accl[mt][n][1] = 0u;
                }
        }

        const uint32_t eb = smE + (uint32_t)(g & 1) * EBUF_BYTES;

#pragma unroll
        for (int ks = 0; ks < 4; ks++) {
            // A fragments (hi/lo) for 2 m-tiles
            uint32_t ah[2][4], al[2][4];
#pragma unroll
            for (int mt = 0; mt < 2; mt++) {
                uint32_t base = smX + a_lane
                              + (uint32_t)(mw * 32 + mt * 16) * (XSTRIDE * 2)
                              + (uint32_t)(c * BD + ks * 16) * 2;
                ldsm_x4(ah[mt], base);
                ldsm_x4(al[mt], base + XSPLIT_BYTES);
            }
            // B fragments (hi/lo): one NON-trans x4 per split -> 16 codes
            uint32_t bh[4], bl[4];
            {
                uint32_t base = eb + b_lane
                              + (uint32_t)(nw * 16) * (ESTRIDE * 2)
                              + (uint32_t)(ks * 16) * 2;
                ldsm_x4(bh, base);
                ldsm_x4(bl, base + ESPLIT_BYTES);
            }
#pragma unroll
            for (int mt = 0; mt < 2; mt++)
#pragma unroll
                for (int n = 0; n < 2; n++) {
                    uint32_t b0h = bh[n * 2], b1h = bh[n * 2 + 1];
                    uint32_t b0l = bl[n * 2], b1l = bl[n * 2 + 1];
                    mma_f32acc(acc[mt][n],  ah[mt], b0h, b1h);   // hi*hi (fp32)
                    mma_f16acc(accl[mt][n], ah[mt], b0l, b1l);   // hi*lo (fp16)
                    mma_f16acc(accl[mt][n], al[mt], b0h, b1h);   // lo*hi (fp16)
                }
        }

        // ---- per-tile argmin epilogue (registers only) ----
        if (c == 3) {
            const int kb = kt0 + nw * 16;
#pragma unroll
            for (int n = 0; n < 2; n++) {
                const int c0 = kb + n * 8 + 2 * tc;
                float2 es = *(const float2*)&g_esq[c0];
#pragma unroll
                for (int mt = 0; mt < 2; mt++) {
                    float2 lo01 = __half22float2(*(__half2*)&accl[mt][n][0]);
                    float2 lo23 = __half22float2(*(__half2*)&accl[mt][n][1]);
                    float d0 = fmaf(-2.0f, acc[mt][n][0] + lo01.x, es.x);
                    float d1 = fmaf(-2.0f, acc[mt][n][1] + lo01.y, es.y);
                    float d2 = fmaf(-2.0f, acc[mt][n][2] + lo23.x, es.x);
                    float d3 = fmaf(-2.0f, acc[mt][n][3] + lo23.y, es.y);
                    int s0 = mt * 2, s1 = mt * 2 + 1;
                    if (d0 < best_d[s0]) { best_d[s0] = d0; best_i[s0] = c0; }
                    if (d1 < best_d[s0]) { best_d[s0] = d1; best_i[s0] = c0 + 1; }
                    if (d2 < best_d[s1]) { best_d[s1] = d2; best_i[s1] = c0; }
                    if (d3 < best_d[s1]) { best_d[s1] = d3; best_i[s1] = c0 + 1; }
                }
            }
        }
        __syncthreads();   // reads of buffer (g&1) done before refill
    }

    // ---- reduce across the 4 tc-lanes of each row group ----
#pragma unroll
    for (int s = 0; s < 4; s++) {
        float d = best_d[s];
        int   i = best_i[s];
#pragma unroll
        for (int off = 1; off <= 2; off <<= 1) {
            float od = __shfl_xor_sync(0xffffffffu, d, off);
            int   oi = __shfl_xor_sync(0xffffffffu, i, off);
            if (od < d || (od == d && oi < i)) { d = od; i = oi; }
        }
        if (tc == 0) {
            int row_local = mw * 32 + (s >> 1) * 16 + (s & 1) * 8 + gr;
            sd[nw][row_local] = d;
            si[nw][row_local] = i;
        }
    }
    __syncthreads();

    // ---- combine the four N-warps, write float32 indices ----
    if (tid < TILE_M) {
        float bd = sd[0][tid];
        int   bi = si[0][tid];
#pragma unroll
        for (int w = 1; w < 4; w++) {
            float d2 = sd[w][tid];
            int   i2 = si[w][tid];
            if (d2 < bd || (d2 == bd && i2 < bi)) { bd = d2; bi = i2; }
        }
        out[row0 + tid] = (float)bi;
    }
}

// ---------------------------------------------------------------------------
// launch
// ---------------------------------------------------------------------------
extern "C" void kernel_launch(void* const* d_in, const int* in_sizes, int n_in,
                              void* d_out, int out_size) {
    // `inputs` is the larger buffer (N=32768 rows vs K=8192 rows).
    const float* x;
    const float* e;
    int N, K;
    if (in_sizes[0] >= in_sizes[1]) {
        x = (const float*)d_in[0]; N = in_sizes[0] / DD;
        e = (const float*)d_in[1]; K = in_sizes[1] / DD;
    } else {
        x = (const float*)d_in[1]; N = in_sizes[1] / DD;
        e = (const float*)d_in[0]; K = in_sizes[0] / DD;
    }
    float* out = (float*)d_out;

    __half *xh, *xl, *eh, *el;
    cudaGetSymbolAddress((void**)&xh, g_xh);
    cudaGetSymbolAddress((void**)&xl, g_xl);
    cudaGetSymbolAddress((void**)&eh, g_eh);
    cudaGetSymbolAddress((void**)&el, g_el);

    const int nx = N * DD, ne = K * DD;
    split_kernel<<<(nx + 255) / 256, 256>>>(x, xh, xl, nx);
    split_kernel<<<(ne + 255) / 256, 256>>>(e, eh, el, ne);
    esq_kernel<<<(K + 255) / 256, 256>>>(e, K);

    cudaFuncSetAttribute(vq_mma_kernel,
                         cudaFuncAttributeMaxDynamicSharedMemorySize, SMEM_BYTES);
    vq_mma_kernel<<<N / TILE_M, NT, SMEM_BYTES>>>(out, N, K);
}

// round 11
// speedup vs baseline: 1.8750x; 1.8643x over previous
#include <cuda_runtime.h>
#include <cuda_fp16.h>
#include <float.h>
#include <stdint.h>

// VectorQuantizer: filter (fp16 hi-product GEMM + rigorous margin) -> refine
// (exact fp32 on ~10 candidates/row).
// out[n] = (float) argmin_k ( e_sq[k] - 2 * <x_n, e_k> )
// Pass-1 error bound: |d_hi - d_true| <= m_r = 2^-9 * ||x_r|| * max_k ||e_k||.
// Collect k if d_hi(k) < gate_r + 2*m_r + eps  (provably includes true argmin).

#define DD      256
#define NMAX    32768
#define KMAX    8192
#define CAP     64                 // candidate slots per row

#define TILE_M  64                 // rows per CTA
#define TILE_NC 128                // codes per K-tile
#define BD      64                 // depth per chunk
#define NT      256                // 8 warps: 2 (M) x 4 (N), 32x32 warp tiles

#define XSTRIDE       264          // fp16 per x row (256 + 8 pad)
#define ESTRIDE       72           // fp16 per e row (64 + 8 pad)
#define XBYTES        (TILE_M * XSTRIDE * 2)    // 33792
#define EBUF_BYTES    (TILE_NC * ESTRIDE * 2)   // 18432
#define SM_E          XBYTES
#define SMEM_BYTES    (SM_E + 2 * EBUF_BYTES)   // 70656

#define DOFF    16384.0f           // distance offset -> positive floats (monotone bits)

__device__ float  g_esq[KMAX];
__device__ float  g_xsq[NMAX];
__device__ float  g_esqmax;
__device__ int    g_count[NMAX];
__device__ int    g_cand[(size_t)NMAX * CAP];
__device__ __half g_xh[(size_t)NMAX * DD];
__device__ __half g_eh[(size_t)KMAX * DD];

// ---------------------------------------------------------------------------
// helpers
// ---------------------------------------------------------------------------
__device__ __forceinline__ uint32_t smem_u32(const void* p) {
    uint32_t a;
    asm("{ .reg .u64 t; cvta.to.shared.u64 t, %1; cvt.u32.u64 %0, t; }"
        : "=r"(a) : "l"(p));
    return a;
}
__device__ __forceinline__ void ldsm_x4(uint32_t* r, uint32_t addr) {
    asm volatile("ldmatrix.sync.aligned.m8n8.x4.shared.b16 {%0,%1,%2,%3}, [%4];"
                 : "=r"(r[0]), "=r"(r[1]), "=r"(r[2]), "=r"(r[3]) : "r"(addr));
}
__device__ __forceinline__ void mma_f32acc(float* d, const uint32_t* a, uint32_t b0, uint32_t b1) {
    asm volatile(
        "mma.sync.aligned.m16n8k16.row.col.f32.f16.f16.f32 "
        "{%0,%1,%2,%3}, {%4,%5,%6,%7}, {%8,%9}, {%0,%1,%2,%3};"
        : "+f"(d[0]), "+f"(d[1]), "+f"(d[2]), "+f"(d[3])
        : "r"(a[0]), "r"(a[1]), "r"(a[2]), "r"(a[3]), "r"(b0), "r"(b1));
}
__device__ __forceinline__ void cp16(uint32_t dst, const void* src) {
    asm volatile("cp.async.cg.shared.global [%0], [%1], 16;"
                 :: "r"(dst), "l"(__cvta_generic_to_global(src)) : "memory");
}

// ---------------------------------------------------------------------------
// precompute kernels
// ---------------------------------------------------------------------------
__global__ void zero_kernel(int n) {
    int i = blockIdx.x * blockDim.x + threadIdx.x;
    if (i < n) g_count[i] = 0;
    if (i == 0) g_esqmax = 0.0f;
}
__global__ void sq_kernel(const float* __restrict__ v, float* __restrict__ sq,
                          int rows, int do_max) {
    int k = blockIdx.x * blockDim.x + threadIdx.x;
    if (k >= rows) return;
    const float* row = v + (size_t)k * DD;
    float s = 0.0f;
#pragma unroll 8
    for (int d = 0; d < DD; d++) s += row[d] * row[d];
    sq[k] = s;
    if (do_max) atomicMax((int*)&g_esqmax, __float_as_int(s));  // s >= 0
}
__global__ void tohalf_kernel(const float* __restrict__ src,
                              __half* __restrict__ dst, int n) {
    int i = blockIdx.x * blockDim.x + threadIdx.x;
    if (i < n) dst[i] = __float2half(src[i]);
}

// ---------------------------------------------------------------------------
// Pass 1: hi-product GEMM + candidate collection
// ---------------------------------------------------------------------------
__global__ __launch_bounds__(NT, 2)
void vq_filter_kernel(int N, int K) {
    extern __shared__ __align__(128) char smem[];
    __shared__ unsigned int s_gate[TILE_M];   // bits of (d_hi + DOFF), monotone
    __shared__ float        s_thradd[TILE_M]; // 2*m_r + eps

    const int tid  = threadIdx.x;
    const int wid  = tid >> 5;
    const int lane = tid & 31;
    const int gr   = lane >> 2;
    const int tc   = lane & 3;
    const int mw   = wid >> 2;        // 0..1 (M slice: mw*32)
    const int nw   = wid & 3;         // 0..3 (N slice: nw*32)
    const int row0 = blockIdx.x * TILE_M;

    const uint32_t smb = smem_u32(smem);
    const uint32_t smX = smb;
    const uint32_t smE = smb + SM_E;

    // init gates + per-row margins
    if (tid < TILE_M) {
        s_gate[tid] = 0xFFFFFFFFu;
        float m = 0.001953125f * sqrtf(g_xsq[row0 + tid] * g_esqmax);  // 2^-9
        s_thradd[tid] = 2.0f * m + 0.125f;
    }

    // resident x_hi tile
    {
        const uint4* xh4 = (const uint4*)g_xh;
#pragma unroll
        for (int t = 0; t < 8; t++) {
            int idx = tid + t * NT;          // 0..2047
            int r   = idx >> 5;
            int g16 = idx & 31;
            size_t g = (size_t)(row0 + r) * 32 + g16;
            *(uint4*)(smem + (uint32_t)r * (XSTRIDE * 2) + (uint32_t)g16 * 16) = xh4[g];
        }
    }

    const uint32_t a_lane = (uint32_t)(lane & 15) * (XSTRIDE * 2) + (uint32_t)(lane & 16);
    const uint32_t b_lane = ((uint32_t)((lane & 7) + ((lane & 16) >> 1))) * (ESTRIDE * 2)
                          + (uint32_t)((lane & 8) << 1);

    const int n_tiles = K / TILE_NC;          // 64
    const int G       = n_tiles * (DD / BD);  // 256

    float acc[2][4][4];                       // [mt][nfrag][v]

    auto issue_load = [&](int g) {
        int c   = g & 3;
        int kt0 = (g >> 2) * TILE_NC;
        uint32_t dbase = smE + (uint32_t)(g & 1) * EBUF_BYTES;
#pragma unroll
        for (int t = 0; t < 4; t++) {
            int idx = tid + t * NT;          // 0..1023
            int j   = idx >> 3;              // code row 0..127
            int g16 = idx & 7;
            const __half* src = g_eh + (size_t)(kt0 + j) * DD + c * BD + g16 * 8;
            cp16(dbase + (uint32_t)j * (ESTRIDE * 2) + (uint32_t)g16 * 16, src);
        }
        asm volatile("cp.async.commit_group;" ::: "memory");
    };

    issue_load(0);

    for (int g = 0; g < G; g++) {
        const int c   = g & 3;
        const int kt0 = (g >> 2) * TILE_NC;

        if (g + 1 < G) {
            issue_load(g + 1);
            asm volatile("cp.async.wait_group 1;" ::: "memory");
        } else {
            asm volatile("cp.async.wait_group 0;" ::: "memory");
        }
        __syncthreads();

        if (c == 0) {
#pragma unroll
            for (int mt = 0; mt < 2; mt++)
#pragma unroll
                for (int n = 0; n < 4; n++)
#pragma unroll
                    for (int v = 0; v < 4; v++) acc[mt][n][v] = 0.0f;
        }

        const uint32_t eb = smE + (uint32_t)(g & 1) * EBUF_BYTES;

#pragma unroll
        for (int ks = 0; ks < 4; ks++) {
            uint32_t ah[2][4];
#pragma unroll
            for (int mt = 0; mt < 2; mt++)
                ldsm_x4(ah[mt], smX + a_lane
                        + (uint32_t)(mw * 32 + mt * 16) * (XSTRIDE * 2)
                        + (uint32_t)(c * BD + ks * 16) * 2);
            uint32_t bh[2][4];
#pragma unroll
            for (int np = 0; np < 2; np++)
                ldsm_x4(bh[np], eb + b_lane
                        + (uint32_t)(nw * 32 + np * 16) * (ESTRIDE * 2)
                        + (uint32_t)(ks * 16) * 2);
#pragma unroll
            for (int mt = 0; mt < 2; mt++)
#pragma unroll
                for (int n = 0; n < 4; n++)
                    mma_f32acc(acc[mt][n], ah[mt], bh[n >> 1][(n & 1) * 2],
                               bh[n >> 1][(n & 1) * 2 + 1]);
        }

        // ---- tile epilogue: gate update (phase 1) + collection (phase 2) ----
        if (c == 3) {
            const int kb = kt0 + nw * 32;
            float dv[2][4][4];
            // compute distances, per-slot local min, atomicMin into gate
#pragma unroll
            for (int mt = 0; mt < 2; mt++) {
                float mn0 = FLT_MAX, mn1 = FLT_MAX;
#pragma unroll
                for (int n = 0; n < 4; n++) {
                    const int c0 = kb + n * 8 + 2 * tc;
                    float2 es = *(const float2*)&g_esq[c0];
                    dv[mt][n][0] = fmaf(-2.0f, acc[mt][n][0], es.x);
                    dv[mt][n][1] = fmaf(-2.0f, acc[mt][n][1], es.y);
                    dv[mt][n][2] = fmaf(-2.0f, acc[mt][n][2], es.x);
                    dv[mt][n][3] = fmaf(-2.0f, acc[mt][n][3], es.y);
                    mn0 = fminf(mn0, fminf(dv[mt][n][0], dv[mt][n][1]));
                    mn1 = fminf(mn1, fminf(dv[mt][n][2], dv[mt][n][3]));
                }
                int r0 = mw * 32 + mt * 16 + gr;
                atomicMin(&s_gate[r0],     __float_as_uint(mn0 + DOFF));
                atomicMin(&s_gate[r0 + 8], __float_as_uint(mn1 + DOFF));
            }
            __syncthreads();   // all gates include this tile
#pragma unroll
            for (int mt = 0; mt < 2; mt++) {
                int r0 = mw * 32 + mt * 16 + gr;
                float thr0 = __uint_as_float(s_gate[r0])     - DOFF + s_thradd[r0];
                float thr1 = __uint_as_float(s_gate[r0 + 8]) - DOFF + s_thradd[r0 + 8];
#pragma unroll
                for (int n = 0; n < 4; n++) {
                    const int c0 = kb + n * 8 + 2 * tc;
                    if (dv[mt][n][0] < thr0) {
                        int p = atomicAdd(&g_count[row0 + r0], 1);
                        if (p < CAP) g_cand[(size_t)(row0 + r0) * CAP + p] = c0;
                    }
                    if (dv[mt][n][1] < thr0) {
                        int p = atomicAdd(&g_count[row0 + r0], 1);
                        if (p < CAP) g_cand[(size_t)(row0 + r0) * CAP + p] = c0 + 1;
                    }
                    if (dv[mt][n][2] < thr1) {
                        int p = atomicAdd(&g_count[row0 + r0 + 8], 1);
                        if (p < CAP) g_cand[(size_t)(row0 + r0 + 8) * CAP + p] = c0;
                    }
                    if (dv[mt][n][3] < thr1) {
                        int p = atomicAdd(&g_count[row0 + r0 + 8], 1);
                        if (p < CAP) g_cand[(size_t)(row0 + r0 + 8) * CAP + p] = c0 + 1;
                    }
                }
            }
        }
        __syncthreads();
    }
}

// ---------------------------------------------------------------------------
// Pass 2: exact fp32 refine over candidates (one warp per row)
// ---------------------------------------------------------------------------
__global__ __launch_bounds__(256)
void refine_kernel(const float* __restrict__ x, const float* __restrict__ e,
                   float* __restrict__ out, int N, int K) {
    int w    = (blockIdx.x * blockDim.x + threadIdx.x) >> 5;
    int lane = threadIdx.x & 31;
    if (w >= N) return;

    // x row: 8 floats per lane
    float xr[8];
    {
        const float4* p = (const float4*)(x + (size_t)w * DD + lane * 8);
        float4 a = p[0], b = p[1];
        xr[0]=a.x; xr[1]=a.y; xr[2]=a.z; xr[3]=a.w;
        xr[4]=b.x; xr[5]=b.y; xr[6]=b.z; xr[7]=b.w;
    }

    int cnt = g_count[w];
    float bd = FLT_MAX;
    int   bi = 0x7FFFFFFF;

    auto eval = [&](int k) {
        const float4* p = (const float4*)(e + (size_t)k * DD + lane * 8);
        float4 a = p[0], b = p[1];
        float s = xr[0]*a.x + xr[1]*a.y + xr[2]*a.z + xr[3]*a.w
                + xr[4]*b.x + xr[5]*b.y + xr[6]*b.z + xr[7]*b.w;
#pragma unroll
        for (int off = 16; off > 0; off >>= 1)
            s += __shfl_xor_sync(0xffffffffu, s, off);
        float d = fmaf(-2.0f, s, g_esq[k]);
        if (d < bd || (d == bd && k < bi)) { bd = d; bi = k; }
    };

    if (cnt >= CAP) {
        for (int k = 0; k < K; k++) eval(k);      // rare safety path
    } else {
        for (int i = 0; i < cnt; i++) eval(g_cand[(size_t)w * CAP + i]);
    }
    if (lane == 0) out[w] = (float)bi;
}

// ---------------------------------------------------------------------------
// launch
// ---------------------------------------------------------------------------
extern "C" void kernel_launch(void* const* d_in, const int* in_sizes, int n_in,
                              void* d_out, int out_size) {
    // `inputs` is the larger buffer (N=32768 rows vs K=8192 rows).
    const float* x;
    const float* e;
    int N, K;
    if (in_sizes[0] >= in_sizes[1]) {
        x = (const float*)d_in[0]; N = in_sizes[0] / DD;
        e = (const float*)d_in[1]; K = in_sizes[1] / DD;
    } else {
        x = (const float*)d_in[1]; N = in_sizes[1] / DD;
        e = (const float*)d_in[0]; K = in_sizes[0] / DD;
    }
    float* out = (float*)d_out;

    float *esq, *xsq;
    __half *xh, *eh;
    cudaGetSymbolAddress((void**)&esq, g_esq);
    cudaGetSymbolAddress((void**)&xsq, g_xsq);
    cudaGetSymbolAddress((void**)&xh,  g_xh);
    cudaGetSymbolAddress((void**)&eh,  g_eh);

    const int nx = N * DD, ne = K * DD;
    zero_kernel<<<(N + 255) / 256, 256>>>(N);
    sq_kernel<<<(K + 255) / 256, 256>>>(e, esq, K, 1);
    sq_kernel<<<(N + 255) / 256, 256>>>(x, xsq, N, 0);
    tohalf_kernel<<<(nx + 255) / 256, 256>>>(x, xh, nx);
    tohalf_kernel<<<(ne + 255) / 256, 256>>>(e, eh, ne);

    cudaFuncSetAttribute(vq_filter_kernel,
                         cudaFuncAttributeMaxDynamicSharedMemorySize, SMEM_BYTES);
    vq_filter_kernel<<<N / TILE_M, NT, SMEM_BYTES>>>(N, K);
    refine_kernel<<<(N * 32 + 255) / 256, 256>>>(x, e, out, N, K);
}

// round 13
// speedup vs baseline: 2.2117x; 1.1796x over previous
#include <cuda_runtime.h>
#include <cuda_fp16.h>
#include <float.h>
#include <stdint.h>
#include <string.h>

// VectorQuantizer: filter (fp16 hi-product GEMM + rigorous margin) -> refine
// (exact fp32 on ~10 candidates/row).
// Pass-1 bound: |d_hi - d_true| <= m_r = 2^-9 * ||x_r|| * max_k ||e_k||.
// R13: R12 with the __half2_as_uint portability fix (bit-copy instead).

#define DD      256
#define NMAX    32768
#define KMAX    8192
#define CAP     64

#define TILE_M  64
#define TILE_NC 256
#define BD      64
#define NT      256               // 8 warps: 2 (M) x 4 (N), 32x64 warp tiles

#define XSTRIDE       264          // fp16 per x row (256 + 8 pad)
#define ESTRIDE       72           // fp16 per e row (64 + 8 pad)
#define XBYTES        (TILE_M * XSTRIDE * 2)    // 33792
#define EBUF_BYTES    (TILE_NC * ESTRIDE * 2)   // 36864
#define SM_E          XBYTES
#define SMEM_BYTES    (SM_E + 2 * EBUF_BYTES)   // 107520

#define DOFF    16384.0f

__device__ float  g_esq[KMAX];
__device__ float  g_xsq[NMAX];
__device__ float  g_esqmax;
__device__ int    g_count[NMAX];
__device__ int    g_cand[(size_t)NMAX * CAP];
__device__ __half g_xh[(size_t)NMAX * DD];
__device__ __half g_eh[(size_t)KMAX * DD];

// ---------------------------------------------------------------------------
// helpers
// ---------------------------------------------------------------------------
__device__ __forceinline__ uint32_t smem_u32(const void* p) {
    uint32_t a;
    asm("{ .reg .u64 t; cvta.to.shared.u64 t, %1; cvt.u32.u64 %0, t; }"
        : "=r"(a) : "l"(p));
    return a;
}
__device__ __forceinline__ uint32_t h2_bits(__half2 h) {
    uint32_t u;
    memcpy(&u, &h, 4);
    return u;
}
__device__ __forceinline__ void ldsm_x4(uint32_t* r, uint32_t addr) {
    asm volatile("ldmatrix.sync.aligned.m8n8.x4.shared.b16 {%0,%1,%2,%3}, [%4];"
                 : "=r"(r[0]), "=r"(r[1]), "=r"(r[2]), "=r"(r[3]) : "r"(addr));
}
__device__ __forceinline__ void mma_f32acc(float* d, const uint32_t* a, uint32_t b0, uint32_t b1) {
    asm volatile(
        "mma.sync.aligned.m16n8k16.row.col.f32.f16.f16.f32 "
        "{%0,%1,%2,%3}, {%4,%5,%6,%7}, {%8,%9}, {%0,%1,%2,%3};"
        : "+f"(d[0]), "+f"(d[1]), "+f"(d[2]), "+f"(d[3])
        : "r"(a[0]), "r"(a[1]), "r"(a[2]), "r"(a[3]), "r"(b0), "r"(b1));
}
__device__ __forceinline__ void cp16(uint32_t dst, const void* src) {
    asm volatile("cp.async.cg.shared.global [%0], [%1], 16;"
                 :: "r"(dst), "l"(__cvta_generic_to_global(src)) : "memory");
}

// ---------------------------------------------------------------------------
// fused preprocessing: one warp per row -> fp16 copy + squared norm
// ---------------------------------------------------------------------------
__global__ void zmax_kernel() { g_esqmax = 0.0f; }

__global__ void prep_kernel(const float* __restrict__ src,
                            __half* __restrict__ dst,
                            float* __restrict__ sq,
                            int rows, int mode /*0=x (zero count), 1=e (max)*/) {
    int w    = (blockIdx.x * blockDim.x + threadIdx.x) >> 5;
    int lane = threadIdx.x & 31;
    if (w >= rows) return;
    const float4* p = (const float4*)(src + (size_t)w * DD + lane * 8);
    float4 a = p[0], b = p[1];
    float s = a.x*a.x + a.y*a.y + a.z*a.z + a.w*a.w
            + b.x*b.x + b.y*b.y + b.z*b.z + b.w*b.w;
#pragma unroll
    for (int off = 16; off > 0; off >>= 1)
        s += __shfl_xor_sync(0xffffffffu, s, off);

    uint4 hv;
    hv.x = h2_bits(__floats2half2_rn(a.x, a.y));
    hv.y = h2_bits(__floats2half2_rn(a.z, a.w));
    hv.z = h2_bits(__floats2half2_rn(b.x, b.y));
    hv.w = h2_bits(__floats2half2_rn(b.z, b.w));
    *(uint4*)(dst + (size_t)w * DD + lane * 8) = hv;

    if (lane == 0) {
        sq[w] = s;
        if (mode == 0) g_count[w] = 0;
        else           atomicMax((int*)&g_esqmax, __float_as_int(s));  // s >= 0
    }
}

// ---------------------------------------------------------------------------
// Pass 1: hi-product GEMM + candidate collection
// ---------------------------------------------------------------------------
__global__ __launch_bounds__(NT, 2)
void vq_filter_kernel(int N, int K) {
    extern __shared__ __align__(128) char smem[];
    __shared__ unsigned int s_gate[TILE_M];
    __shared__ float        s_thradd[TILE_M];

    const int tid  = threadIdx.x;
    const int wid  = tid >> 5;
    const int lane = tid & 31;
    const int gr   = lane >> 2;
    const int tc   = lane & 3;
    const int mw   = wid >> 2;        // 0..1 (M slice: mw*32)
    const int nw   = wid & 3;         // 0..3 (N slice: nw*64)
    const int row0 = blockIdx.x * TILE_M;

    const uint32_t smb = smem_u32(smem);
    const uint32_t smX = smb;
    const uint32_t smE = smb + SM_E;

    if (tid < TILE_M) {
        s_gate[tid] = 0xFFFFFFFFu;
        float m = 0.001953125f * sqrtf(g_xsq[row0 + tid] * g_esqmax);  // 2^-9
        s_thradd[tid] = 2.0f * m + 0.125f;
    }

    // resident x_hi tile
    {
        const uint4* xh4 = (const uint4*)g_xh;
#pragma unroll
        for (int t = 0; t < 8; t++) {
            int idx = tid + t * NT;
            int r   = idx >> 5;
            int g16 = idx & 31;
            size_t g = (size_t)(row0 + r) * 32 + g16;
            *(uint4*)(smem + (uint32_t)r * (XSTRIDE * 2) + (uint32_t)g16 * 16) = xh4[g];
        }
    }

    const uint32_t a_lane = (uint32_t)(lane & 15) * (XSTRIDE * 2) + (uint32_t)(lane & 16);
    const uint32_t b_lane = ((uint32_t)((lane & 7) + ((lane & 16) >> 1))) * (ESTRIDE * 2)
                          + (uint32_t)((lane & 8) << 1);

    const int n_tiles = K / TILE_NC;          // 32
    const int G       = n_tiles * (DD / BD);  // 128

    float acc[2][8][4];                       // 32x64 warp tile

    auto issue_load = [&](int g) {
        int c   = g & 3;
        int kt0 = (g >> 2) * TILE_NC;
        uint32_t dbase = smE + (uint32_t)(g & 1) * EBUF_BYTES;
#pragma unroll
        for (int t = 0; t < 8; t++) {
            int idx = tid + t * NT;          // 0..2047
            int j   = idx >> 3;              // code row 0..255
            int g16 = idx & 7;
            const __half* src = g_eh + (size_t)(kt0 + j) * DD + c * BD + g16 * 8;
            cp16(dbase + (uint32_t)j * (ESTRIDE * 2) + (uint32_t)g16 * 16, src);
        }
        asm volatile("cp.async.commit_group;" ::: "memory");
    };

    issue_load(0);

    for (int g = 0; g < G; g++) {
        const int c   = g & 3;
        const int kt0 = (g >> 2) * TILE_NC;

        if (g + 1 < G) {
            issue_load(g + 1);
            asm volatile("cp.async.wait_group 1;" ::: "memory");
        } else {
            asm volatile("cp.async.wait_group 0;" ::: "memory");
        }
        __syncthreads();

        if (c == 0) {
#pragma unroll
            for (int mt = 0; mt < 2; mt++)
#pragma unroll
                for (int n = 0; n < 8; n++)
#pragma unroll
                    for (int v = 0; v < 4; v++) acc[mt][n][v] = 0.0f;
        }

        const uint32_t eb = smE + (uint32_t)(g & 1) * EBUF_BYTES;

#pragma unroll
        for (int ks = 0; ks < 4; ks++) {
            uint32_t ah[2][4];
#pragma unroll
            for (int mt = 0; mt < 2; mt++)
                ldsm_x4(ah[mt], smX + a_lane
                        + (uint32_t)(mw * 32 + mt * 16) * (XSTRIDE * 2)
                        + (uint32_t)(c * BD + ks * 16) * 2);
            uint32_t bh[4][4];
#pragma unroll
            for (int np = 0; np < 4; np++)
                ldsm_x4(bh[np], eb + b_lane
                        + (uint32_t)(nw * 64 + np * 16) * (ESTRIDE * 2)
                        + (uint32_t)(ks * 16) * 2);
#pragma unroll
            for (int mt = 0; mt < 2; mt++)
#pragma unroll
                for (int n = 0; n < 8; n++)
                    mma_f32acc(acc[mt][n], ah[mt], bh[n >> 1][(n & 1) * 2],
                               bh[n >> 1][(n & 1) * 2 + 1]);
        }

        if (c == 3) {
            const int kb = kt0 + nw * 64;
            // phase 1: per-slot mins -> gate
#pragma unroll
            for (int mt = 0; mt < 2; mt++) {
                float mn0 = FLT_MAX, mn1 = FLT_MAX;
#pragma unroll
                for (int n = 0; n < 8; n++) {
                    const int c0 = kb + n * 8 + 2 * tc;
                    float2 es = *(const float2*)&g_esq[c0];
                    mn0 = fminf(mn0, fminf(fmaf(-2.0f, acc[mt][n][0], es.x),
                                           fmaf(-2.0f, acc[mt][n][1], es.y)));
                    mn1 = fminf(mn1, fminf(fmaf(-2.0f, acc[mt][n][2], es.x),
                                           fmaf(-2.0f, acc[mt][n][3], es.y)));
                }
                int r0 = mw * 32 + mt * 16 + gr;
                atomicMin(&s_gate[r0],     __float_as_uint(mn0 + DOFF));
                atomicMin(&s_gate[r0 + 8], __float_as_uint(mn1 + DOFF));
            }
            __syncthreads();
            // phase 2: recompute + collect
#pragma unroll
            for (int mt = 0; mt < 2; mt++) {
                int r0 = mw * 32 + mt * 16 + gr;
                float thr0 = __uint_as_float(s_gate[r0])     - DOFF + s_thradd[r0];
                float thr1 = __uint_as_float(s_gate[r0 + 8]) - DOFF + s_thradd[r0 + 8];
#pragma unroll
                for (int n = 0; n < 8; n++) {
                    const int c0 = kb + n * 8 + 2 * tc;
                    float2 es = *(const float2*)&g_esq[c0];
                    float d0 = fmaf(-2.0f, acc[mt][n][0], es.x);
                    float d1 = fmaf(-2.0f, acc[mt][n][1], es.y);
                    float d2 = fmaf(-2.0f, acc[mt][n][2], es.x);
                    float d3 = fmaf(-2.0f, acc[mt][n][3], es.y);
                    if (d0 < thr0) {
                        int p = atomicAdd(&g_count[row0 + r0], 1);
                        if (p < CAP) g_cand[(size_t)(row0 + r0) * CAP + p] = c0;
                    }
                    if (d1 < thr0) {
                        int p = atomicAdd(&g_count[row0 + r0], 1);
                        if (p < CAP) g_cand[(size_t)(row0 + r0) * CAP + p] = c0 + 1;
                    }
                    if (d2 < thr1) {
                        int p = atomicAdd(&g_count[row0 + r0 + 8], 1);
                        if (p < CAP) g_cand[(size_t)(row0 + r0 + 8) * CAP + p] = c0;
                    }
                    if (d3 < thr1) {
                        int p = atomicAdd(&g_count[row0 + r0 + 8], 1);
                        if (p < CAP) g_cand[(size_t)(row0 + r0 + 8) * CAP + p] = c0 + 1;
                    }
                }
            }
        }
        __syncthreads();
    }
}

// ---------------------------------------------------------------------------
// Pass 2: exact fp32 refine over candidates (one warp per row)
// ---------------------------------------------------------------------------
__global__ __launch_bounds__(256)
void refine_kernel(const float* __restrict__ x, const float* __restrict__ e,
                   float* __restrict__ out, int N, int K) {
    int w    = (blockIdx.x * blockDim.x + threadIdx.x) >> 5;
    int lane = threadIdx.x & 31;
    if (w >= N) return;

    float xr[8];
    {
        const float4* p = (const float4*)(x + (size_t)w * DD + lane * 8);
        float4 a = p[0], b = p[1];
        xr[0]=a.x; xr[1]=a.y; xr[2]=a.z; xr[3]=a.w;
        xr[4]=b.x; xr[5]=b.y; xr[6]=b.z; xr[7]=b.w;
    }

    int cnt = g_count[w];
    float bd = FLT_MAX;
    int   bi = 0x7FFFFFFF;

    auto eval = [&](int k) {
        const float4* p = (const float4*)(e + (size_t)k * DD + lane * 8);
        float4 a = p[0], b = p[1];
        float s = xr[0]*a.x + xr[1]*a.y + xr[2]*a.z + xr[3]*a.w
                + xr[4]*b.x + xr[5]*b.y + xr[6]*b.z + xr[7]*b.w;
#pragma unroll
        for (int off = 16; off > 0; off >>= 1)
            s += __shfl_xor_sync(0xffffffffu, s, off);
        float d = fmaf(-2.0f, s, g_esq[k]);
        if (d < bd || (d == bd && k < bi)) { bd = d; bi = k; }
    };

    if (cnt >= CAP) {
        for (int k = 0; k < K; k++) eval(k);
    } else {
        for (int i = 0; i < cnt; i++) eval(g_cand[(size_t)w * CAP + i]);
    }
    if (lane == 0) out[w] = (float)bi;
}

// ---------------------------------------------------------------------------
// launch
// ---------------------------------------------------------------------------
extern "C" void kernel_launch(void* const* d_in, const int* in_sizes, int n_in,
                              void* d_out, int out_size) {
    const float* x;
    const float* e;
    int N, K;
    if (in_sizes[0] >= in_sizes[1]) {
        x = (const float*)d_in[0]; N = in_sizes[0] / DD;
        e = (const float*)d_in[1]; K = in_sizes[1] / DD;
    } else {
        x = (const float*)d_in[1]; N = in_sizes[1] / DD;
        e = (const float*)d_in[0]; K = in_sizes[0] / DD;
    }
    float* out = (float*)d_out;

    float *esq, *xsq;
    __half *xh, *eh;
    cudaGetSymbolAddress((void**)&esq, g_esq);
    cudaGetSymbolAddress((void**)&xsq, g_xsq);
    cudaGetSymbolAddress((void**)&xh,  g_xh);
    cudaGetSymbolAddress((void**)&eh,  g_eh);

    zmax_kernel<<<1, 1>>>();
    prep_kernel<<<(K * 32 + 255) / 256, 256>>>(e, eh, esq, K, 1);
    prep_kernel<<<(N * 32 + 255) / 256, 256>>>(x, xh, xsq, N, 0);

    cudaFuncSetAttribute(vq_filter_kernel,
                         cudaFuncAttributeMaxDynamicSharedMemorySize, SMEM_BYTES);
    vq_filter_kernel<<<N / TILE_M, NT, SMEM_BYTES>>>(N, K);
    refine_kernel<<<(N * 32 + 255) / 256, 256>>>(x, e, out, N, K);
}